// round 3
// baseline (speedup 1.0000x reference)
#include <cuda_runtime.h>
#include <cuda_bf16.h>
#include <math.h>

// ---------------- problem constants ----------------
#define HDIM 128                 // F_IN == H == 128
#define MAXN 50048               // 391 * 128, padded node count
#define MAXNNZ 700000
#define NFEAT_PAD (MAXN * HDIM)

// ---------------- device scratch (allocation-free) ----------------
__device__ float g_deg[MAXN];
__device__ float g_dinv[MAXN];
__device__ int   g_cnt[MAXN];
__device__ int   g_off[MAXN + 1];
__device__ int   g_fill[MAXN];
__device__ int   g_src[MAXNNZ];
__device__ float g_wc[MAXNNZ];
__device__ float g_h[NFEAT_PAD];
__device__ float g_h0[NFEAT_PAD];
__device__ float g_ag[NFEAT_PAD];

// ---------------- graph preprocessing ----------------
__global__ void init_kernel(float* deg, int* cnt, int n) {
    int i = blockIdx.x * blockDim.x + threadIdx.x;
    if (i < n) { deg[i] = 1.0f; cnt[i] = 1; }   // self-loop weight 1, self in-edge
}

__global__ void edge_count_kernel(const int* __restrict__ row, const int* __restrict__ col,
                                  const float* __restrict__ w, float* deg, int* cnt, int E) {
    int e = blockIdx.x * blockDim.x + threadIdx.x;
    if (e < E) {
        atomicAdd(&deg[row[e]], w[e]);
        atomicAdd(&cnt[col[e]], 1);
    }
}

__global__ void dinv_kernel(const float* __restrict__ deg, float* dinv, int n) {
    int i = blockIdx.x * blockDim.x + threadIdx.x;
    if (i < n) dinv[i] = rsqrtf(deg[i]);   // deg >= 1 always
}

// single-block exclusive scan over cnt -> off (and copy to fill)
__global__ void scan_kernel(const int* __restrict__ cnt, int* off, int* fill, int n) {
    __shared__ int sm[1024];
    int carry = 0;
    for (int base = 0; base < n; base += 1024) {
        int i = base + threadIdx.x;
        int v = (i < n) ? cnt[i] : 0;
        sm[threadIdx.x] = v;
        __syncthreads();
        for (int d = 1; d < 1024; d <<= 1) {
            int t = (threadIdx.x >= d) ? sm[threadIdx.x - d] : 0;
            __syncthreads();
            sm[threadIdx.x] += t;
            __syncthreads();
        }
        int excl = carry + sm[threadIdx.x] - v;
        if (i < n) { off[i] = excl; fill[i] = excl; }
        carry += sm[1023];
        __syncthreads();
    }
    if (threadIdx.x == 0) off[n] = carry;
}

__global__ void fill_edges_kernel(const int* __restrict__ row, const int* __restrict__ col,
                                  const float* __restrict__ w, const float* __restrict__ dinv,
                                  int* fill, int* srcv, float* wcsc, int E) {
    int e = blockIdx.x * blockDim.x + threadIdx.x;
    if (e < E) {
        int r = row[e], c = col[e];
        int p = atomicAdd(&fill[c], 1);
        srcv[p] = r;
        wcsc[p] = dinv[r] * w[e] * dinv[c];
    }
}

__global__ void fill_self_kernel(const float* __restrict__ dinv, int* fill,
                                 int* srcv, float* wcsc, int n) {
    int i = blockIdx.x * blockDim.x + threadIdx.x;
    if (i < n) {
        int p = atomicAdd(&fill[i], 1);
        srcv[p] = i;
        wcsc[p] = dinv[i] * dinv[i];
    }
}

// zero padding rows [N, MAXN) of h, h0, ag so guard-free GEMMs read zeros
__global__ void pad_kernel(float* h, float* h0, float* ag, int startElem, int totalElem) {
    int i = blockIdx.x * blockDim.x + threadIdx.x + startElem;
    if (i < totalElem) { h[i] = 0.0f; h0[i] = 0.0f; ag[i] = 0.0f; }
}

// ---------------- SGEMM tiles ----------------
#define BM 128
#define BN 128
#define BK 8
#define TM 8
#define TN 8

// ---- input linear: h = h0 = relu(x @ w_in + b), guarded (x has exactly M rows) ----
__global__ void __launch_bounds__(256, 2)
gemm_in(const float* __restrict__ A, const float* __restrict__ W,
        const float* __restrict__ bias, float* __restrict__ out,
        float* __restrict__ out2, int M) {
    __shared__ float As[BK][BM];
    __shared__ float Bs[BK][BN];
    const int tid = threadIdx.x;
    const int tx = tid & 15, ty = tid >> 4;
    const int m0 = blockIdx.x * BM;
    const int arow = tid >> 1, acol4 = (tid & 1) * 4;
    const int brow = tid >> 5, bcol4 = (tid & 31) * 4;

    float acc[TM][TN];
#pragma unroll
    for (int i = 0; i < TM; i++)
#pragma unroll
        for (int j = 0; j < TN; j++) acc[i][j] = 0.0f;

    for (int k0 = 0; k0 < HDIM; k0 += BK) {
        float4 av = make_float4(0.f, 0.f, 0.f, 0.f);
        int am = m0 + arow;
        if (am < M) av = *reinterpret_cast<const float4*>(A + (size_t)am * HDIM + k0 + acol4);
        As[acol4 + 0][arow] = av.x; As[acol4 + 1][arow] = av.y;
        As[acol4 + 2][arow] = av.z; As[acol4 + 3][arow] = av.w;

        float4 bv = *reinterpret_cast<const float4*>(W + (size_t)(k0 + brow) * HDIM + bcol4);
        Bs[brow][bcol4 + 0] = bv.x; Bs[brow][bcol4 + 1] = bv.y;
        Bs[brow][bcol4 + 2] = bv.z; Bs[brow][bcol4 + 3] = bv.w;
        __syncthreads();

#pragma unroll
        for (int kk = 0; kk < BK; kk++) {
            float ra[TM], rb[TN];
#pragma unroll
            for (int i = 0; i < TM; i++) ra[i] = As[kk][ty * TM + i];
#pragma unroll
            for (int j = 0; j < TN; j++) rb[j] = Bs[kk][tx * TN + j];
#pragma unroll
            for (int i = 0; i < TM; i++)
#pragma unroll
                for (int j = 0; j < TN; j++) acc[i][j] += ra[i] * rb[j];
        }
        __syncthreads();
    }

    float b0[TN];
#pragma unroll
    for (int j = 0; j < TN; j++) b0[j] = bias[tx * TN + j];

#pragma unroll
    for (int i = 0; i < TM; i++) {
        int m = m0 + ty * TM + i;
        if (m >= M) continue;
        float4 o0, o1;
        o0.x = fmaxf(acc[i][0] + b0[0], 0.f); o0.y = fmaxf(acc[i][1] + b0[1], 0.f);
        o0.z = fmaxf(acc[i][2] + b0[2], 0.f); o0.w = fmaxf(acc[i][3] + b0[3], 0.f);
        o1.x = fmaxf(acc[i][4] + b0[4], 0.f); o1.y = fmaxf(acc[i][5] + b0[5], 0.f);
        o1.z = fmaxf(acc[i][6] + b0[6], 0.f); o1.w = fmaxf(acc[i][7] + b0[7], 0.f);
        float4* p  = reinterpret_cast<float4*>(out  + (size_t)m * HDIM + tx * TN);
        float4* p2 = reinterpret_cast<float4*>(out2 + (size_t)m * HDIM + tx * TN);
        p[0] = o0; p[1] = o1; p2[0] = o0; p2[1] = o1;
    }
}

// ---- fused layer GEMM (guard-free, padded M), K = 256 over [ag | h0]:
//   h_out = relu( cs*ag + ci*h0 + beta*( ag@W1 + h0@W2 ) )
__global__ void __launch_bounds__(256, 2)
gemm_layer_fused(const float* __restrict__ ag, const float* __restrict__ h0,
                 const float* __restrict__ W1, const float* __restrict__ W2,
                 float* __restrict__ hout, float cs, float ci, float beta) {
    __shared__ float As[BK][BM];
    __shared__ float Bs[BK][BN];
    const int tid = threadIdx.x;
    const int tx = tid & 15, ty = tid >> 4;
    const int m0 = blockIdx.x * BM;
    const int arow = tid >> 1, acol4 = (tid & 1) * 4;
    const int brow = tid >> 5, bcol4 = (tid & 31) * 4;

    float acc[TM][TN];
#pragma unroll
    for (int i = 0; i < TM; i++)
#pragma unroll
        for (int j = 0; j < TN; j++) acc[i][j] = 0.0f;

#pragma unroll 1
    for (int half = 0; half < 2; half++) {
        const float* A = half ? h0 : ag;
        const float* W = half ? W2 : W1;
        for (int k0 = 0; k0 < HDIM; k0 += BK) {
            float4 av = *reinterpret_cast<const float4*>(A + (size_t)(m0 + arow) * HDIM + k0 + acol4);
            As[acol4 + 0][arow] = av.x; As[acol4 + 1][arow] = av.y;
            As[acol4 + 2][arow] = av.z; As[acol4 + 3][arow] = av.w;

            float4 bv = *reinterpret_cast<const float4*>(W + (size_t)(k0 + brow) * HDIM + bcol4);
            Bs[brow][bcol4 + 0] = bv.x; Bs[brow][bcol4 + 1] = bv.y;
            Bs[brow][bcol4 + 2] = bv.z; Bs[brow][bcol4 + 3] = bv.w;
            __syncthreads();

#pragma unroll
            for (int kk = 0; kk < BK; kk++) {
                float ra[TM], rb[TN];
#pragma unroll
                for (int i = 0; i < TM; i++) ra[i] = As[kk][ty * TM + i];
#pragma unroll
                for (int j = 0; j < TN; j++) rb[j] = Bs[kk][tx * TN + j];
#pragma unroll
                for (int i = 0; i < TM; i++)
#pragma unroll
                    for (int j = 0; j < TN; j++) acc[i][j] += ra[i] * rb[j];
            }
            __syncthreads();
        }
    }

#pragma unroll
    for (int i = 0; i < TM; i++) {
        int m = m0 + ty * TM + i;
        const float4* agr = reinterpret_cast<const float4*>(ag + (size_t)m * HDIM + tx * TN);
        const float4* h0r = reinterpret_cast<const float4*>(h0 + (size_t)m * HDIM + tx * TN);
        float4 a0 = agr[0], a1 = agr[1];
        float4 z0 = h0r[0], z1 = h0r[1];
        float4 o0, o1;
        o0.x = fmaxf(cs * a0.x + ci * z0.x + beta * acc[i][0], 0.f);
        o0.y = fmaxf(cs * a0.y + ci * z0.y + beta * acc[i][1], 0.f);
        o0.z = fmaxf(cs * a0.z + ci * z0.z + beta * acc[i][2], 0.f);
        o0.w = fmaxf(cs * a0.w + ci * z0.w + beta * acc[i][3], 0.f);
        o1.x = fmaxf(cs * a1.x + ci * z1.x + beta * acc[i][4], 0.f);
        o1.y = fmaxf(cs * a1.y + ci * z1.y + beta * acc[i][5], 0.f);
        o1.z = fmaxf(cs * a1.z + ci * z1.z + beta * acc[i][6], 0.f);
        o1.w = fmaxf(cs * a1.w + ci * z1.w + beta * acc[i][7], 0.f);
        float4* p = reinterpret_cast<float4*>(hout + (size_t)m * HDIM + tx * TN);
        p[0] = o0; p[1] = o1;
    }
}

// ---- output linear: out[M,64] = h @ w_out + b_out ----
__global__ void __launch_bounds__(256, 2)
gemm_out(const float* __restrict__ A, const float* __restrict__ W,
         const float* __restrict__ bias, float* __restrict__ out, int M) {
    __shared__ float As[BK][BM];
    __shared__ float Bs[BK][BN];
    const int tid = threadIdx.x;
    const int tx = tid & 15, ty = tid >> 4;
    const int m0 = blockIdx.x * BM;
    const int arow = tid >> 1, acol4 = (tid & 1) * 4;
    const int brow = tid >> 5, bcol4 = (tid & 31) * 4;
    const int Nn = 64;

    float acc[TM][TN];
#pragma unroll
    for (int i = 0; i < TM; i++)
#pragma unroll
        for (int j = 0; j < TN; j++) acc[i][j] = 0.0f;

    for (int k0 = 0; k0 < HDIM; k0 += BK) {
        float4 av = *reinterpret_cast<const float4*>(A + (size_t)(m0 + arow) * HDIM + k0 + acol4);
        As[acol4 + 0][arow] = av.x; As[acol4 + 1][arow] = av.y;
        As[acol4 + 2][arow] = av.z; As[acol4 + 3][arow] = av.w;

        float4 bv = make_float4(0.f, 0.f, 0.f, 0.f);
        if (bcol4 < Nn) bv = *reinterpret_cast<const float4*>(W + (size_t)(k0 + brow) * Nn + bcol4);
        Bs[brow][bcol4 + 0] = bv.x; Bs[brow][bcol4 + 1] = bv.y;
        Bs[brow][bcol4 + 2] = bv.z; Bs[brow][bcol4 + 3] = bv.w;
        __syncthreads();

#pragma unroll
        for (int kk = 0; kk < BK; kk++) {
            float ra[TM], rb[TN];
#pragma unroll
            for (int i = 0; i < TM; i++) ra[i] = As[kk][ty * TM + i];
#pragma unroll
            for (int j = 0; j < TN; j++) rb[j] = Bs[kk][tx * TN + j];
#pragma unroll
            for (int i = 0; i < TM; i++)
#pragma unroll
                for (int j = 0; j < TN; j++) acc[i][j] += ra[i] * rb[j];
        }
        __syncthreads();
    }

    if (tx < 8) {   // only columns < 64
        float b0[TN];
#pragma unroll
        for (int j = 0; j < TN; j++) b0[j] = bias[tx * TN + j];
#pragma unroll
        for (int i = 0; i < TM; i++) {
            int m = m0 + ty * TM + i;
            if (m >= M) continue;
            float4 o0, o1;
            o0.x = acc[i][0] + b0[0]; o0.y = acc[i][1] + b0[1];
            o0.z = acc[i][2] + b0[2]; o0.w = acc[i][3] + b0[3];
            o1.x = acc[i][4] + b0[4]; o1.y = acc[i][5] + b0[5];
            o1.z = acc[i][6] + b0[6]; o1.w = acc[i][7] + b0[7];
            float4* p = reinterpret_cast<float4*>(out + (size_t)m * Nn + tx * TN);
            p[0] = o0; p[1] = o1;
        }
    }
}

// ---------------- atomic-free CSC aggregation: ag[c,:] = sum_j wc[j]*h[src[j],:] ----
// warp per node; lane handles 4 features via float4 (LDG.128).
__global__ void agg_kernel(const float* __restrict__ h,
                           const int* __restrict__ off, const int* __restrict__ src,
                           const float* __restrict__ wc, float* __restrict__ ag, int n) {
    int node = (blockIdx.x * blockDim.x + threadIdx.x) >> 5;
    int lane = threadIdx.x & 31;
    if (node >= n) return;
    int s = off[node], e = off[node + 1];
    const float4* H4 = reinterpret_cast<const float4*>(h);
    float4 acc = make_float4(0.f, 0.f, 0.f, 0.f);
    int j = s;
    for (; j + 1 < e; j += 2) {
        int s0 = src[j], s1 = src[j + 1];
        float w0 = wc[j], w1 = wc[j + 1];
        float4 v0 = H4[(size_t)s0 * 32 + lane];
        float4 v1 = H4[(size_t)s1 * 32 + lane];
        acc.x += w0 * v0.x; acc.y += w0 * v0.y; acc.z += w0 * v0.z; acc.w += w0 * v0.w;
        acc.x += w1 * v1.x; acc.y += w1 * v1.y; acc.z += w1 * v1.z; acc.w += w1 * v1.w;
    }
    if (j < e) {
        float w0 = wc[j];
        float4 v0 = H4[(size_t)src[j] * 32 + lane];
        acc.x += w0 * v0.x; acc.y += w0 * v0.y; acc.z += w0 * v0.z; acc.w += w0 * v0.w;
    }
    reinterpret_cast<float4*>(ag)[(size_t)node * 32 + lane] = acc;
}

// ---------------- log_softmax over 64 classes, in place ----------------
__global__ void logsoftmax64_kernel(float* __restrict__ out, int n) {
    int row = blockIdx.x * 8 + (threadIdx.x >> 5);
    int lane = threadIdx.x & 31;
    if (row >= n) return;
    float* p = out + (size_t)row * 64;
    float a = p[lane], b = p[lane + 32];
    float mx = fmaxf(a, b);
#pragma unroll
    for (int d = 16; d; d >>= 1) mx = fmaxf(mx, __shfl_xor_sync(0xFFFFFFFFu, mx, d));
    float s = __expf(a - mx) + __expf(b - mx);
#pragma unroll
    for (int d = 16; d; d >>= 1) s += __shfl_xor_sync(0xFFFFFFFFu, s, d);
    float lse = mx + __logf(s);
    p[lane] = a - lse;
    p[lane + 32] = b - lse;
}

// ---------------- launch ----------------
extern "C" void kernel_launch(void* const* d_in, const int* in_sizes, int n_in,
                              void* d_out, int out_size) {
    const float* x     = (const float*)d_in[0];
    const int*   ei    = (const int*)  d_in[1];
    const float* ew    = (const float*)d_in[2];
    const float* w_in  = (const float*)d_in[3];
    const float* b_in  = (const float*)d_in[4];
    const float* ws1   = (const float*)d_in[5];
    const float* ws2   = (const float*)d_in[6];
    const float* w_out = (const float*)d_in[7];
    const float* b_out = (const float*)d_in[8];

    const int N = in_sizes[0] / HDIM;            // 50000
    const int E = in_sizes[2];                   // 640000
    const int L = in_sizes[5] / (HDIM * HDIM);   // 16
    const float ALPHA = 0.1f;
    const double LAMDA = 0.5;

    const int* erow = ei;
    const int* ecol = ei + E;

    float *deg, *dinv, *wc, *h, *h0, *ag;
    int *cnt, *off, *fill, *src;
    cudaGetSymbolAddress((void**)&deg,  g_deg);
    cudaGetSymbolAddress((void**)&dinv, g_dinv);
    cudaGetSymbolAddress((void**)&cnt,  g_cnt);
    cudaGetSymbolAddress((void**)&off,  g_off);
    cudaGetSymbolAddress((void**)&fill, g_fill);
    cudaGetSymbolAddress((void**)&src,  g_src);
    cudaGetSymbolAddress((void**)&wc,   g_wc);
    cudaGetSymbolAddress((void**)&h,    g_h);
    cudaGetSymbolAddress((void**)&h0,   g_h0);
    cudaGetSymbolAddress((void**)&ag,   g_ag);

    const int TB = 256;
    const int gN = (N + TB - 1) / TB;
    const int gE = (E + TB - 1) / TB;

    // ---- graph normalization + CSC build ----
    init_kernel<<<gN, TB>>>(deg, cnt, N);
    edge_count_kernel<<<gE, TB>>>(erow, ecol, ew, deg, cnt, E);
    dinv_kernel<<<gN, TB>>>(deg, dinv, N);
    scan_kernel<<<1, 1024>>>(cnt, off, fill, N);
    fill_edges_kernel<<<gE, TB>>>(erow, ecol, ew, dinv, fill, src, wc, E);
    fill_self_kernel<<<gN, TB>>>(dinv, fill, src, wc, N);

    // zero padding rows of h/h0/ag
    {
        int startElem = N * HDIM;
        int padElems = NFEAT_PAD - startElem;
        pad_kernel<<<(padElems + TB - 1) / TB, TB>>>(h, h0, ag, startElem, NFEAT_PAD);
    }

    const int gGemm = MAXN / BM;   // 391, covers padded rows

    // ---- input linear + relu; h and h0 (guarded on M=N) ----
    gemm_in<<<gGemm, 256>>>(x, w_in, b_in, h, h0, N);

    // ---- GCNII layers: ag = A_hat@h, then fused K=256 GEMM ----
    for (int i = 0; i < L; i++) {
        float beta = (float)log(LAMDA / (double)(i + 1) + 1.0);
        float cs = (1.0f - beta) * (1.0f - ALPHA);
        float ci = (1.0f - beta) * ALPHA;
        agg_kernel<<<(N * 32 + 255) / 256, 256>>>(h, off, src, wc, ag, N);
        gemm_layer_fused<<<gGemm, 256>>>(ag, h0,
                                         ws1 + (size_t)i * HDIM * HDIM,
                                         ws2 + (size_t)i * HDIM * HDIM,
                                         h, cs, ci, beta);
    }

    // ---- output linear + log_softmax ----
    float* outp = (float*)d_out;
    gemm_out<<<gGemm, 256>>>(h, w_out, b_out, outp, N);
    logsoftmax64_kernel<<<(N + 7) / 8, 256>>>(outp, N);
}

// round 10
// speedup vs baseline: 1.3777x; 1.3777x over previous
#include <cuda_runtime.h>
#include <cuda_bf16.h>
#include <mma.h>
#include <math.h>

using namespace nvcuda;

// ---------------- problem constants ----------------
#define HDIM 128                 // F_IN == H == 128
#define MAXN 50048               // 391 * 128, padded node count
#define MAXNNZ 700000
#define NFEAT_PAD (MAXN * HDIM)

// ---------------- device scratch (allocation-free) ----------------
__device__ float g_deg[MAXN];
__device__ float g_dinv[MAXN];
__device__ int   g_cnt[MAXN];
__device__ int   g_off[MAXN + 1];
__device__ int   g_fill[MAXN];
__device__ int   g_src[MAXNNZ];
__device__ float g_wc[MAXNNZ];
__device__ float g_h[NFEAT_PAD];
__device__ float g_h0[NFEAT_PAD];
__device__ float g_ag[NFEAT_PAD];
__device__ int   g_bsum[64];
__device__ int   g_boff[65];

// ---------------- graph preprocessing ----------------
__global__ void init_kernel(float* deg, int* cnt, int n) {
    int i = blockIdx.x * blockDim.x + threadIdx.x;
    if (i < n) { deg[i] = 1.0f; cnt[i] = 1; }   // self-loop weight 1, self in-edge
}

__global__ void edge_count_kernel(const int* __restrict__ row, const int* __restrict__ col,
                                  const float* __restrict__ w, float* deg, int* cnt, int E) {
    int e = blockIdx.x * blockDim.x + threadIdx.x;
    if (e < E) {
        atomicAdd(&deg[row[e]], w[e]);
        atomicAdd(&cnt[col[e]], 1);
    }
}

__global__ void dinv_kernel(const float* __restrict__ deg, float* dinv, int n) {
    int i = blockIdx.x * blockDim.x + threadIdx.x;
    if (i < n) dinv[i] = rsqrtf(deg[i]);   // deg >= 1 always
}

// ---- multi-block exclusive scan: per-block scan -> scan of block sums -> fixup ----
__global__ void scan_block_kernel(const int* __restrict__ cnt, int* off, int n) {
    __shared__ int sm[1024];
    int i = blockIdx.x * 1024 + threadIdx.x;
    int v = (i < n) ? cnt[i] : 0;
    sm[threadIdx.x] = v;
    __syncthreads();
#pragma unroll
    for (int d = 1; d < 1024; d <<= 1) {
        int t = (threadIdx.x >= d) ? sm[threadIdx.x - d] : 0;
        __syncthreads();
        sm[threadIdx.x] += t;
        __syncthreads();
    }
    if (i < n) off[i] = sm[threadIdx.x] - v;     // exclusive within block
    if (threadIdx.x == 1023) g_bsum[blockIdx.x] = sm[1023];
}

__global__ void scan_bsums_kernel(int nb) {
    if (threadIdx.x == 0) {
        int acc = 0;
        for (int b = 0; b < nb; b++) { g_boff[b] = acc; acc += g_bsum[b]; }
        g_boff[nb] = acc;
    }
}

__global__ void scan_fixup_kernel(int* off, int* fill, int n, int nb) {
    int i = blockIdx.x * 1024 + threadIdx.x;
    if (i < n) {
        int o = off[i] + g_boff[blockIdx.x];
        off[i] = o; fill[i] = o;
    }
    if (i == 0) off[n] = g_boff[nb];
}

__global__ void fill_edges_kernel(const int* __restrict__ row, const int* __restrict__ col,
                                  const float* __restrict__ w, const float* __restrict__ dinv,
                                  int* fill, int* srcv, float* wcsc, int E) {
    int e = blockIdx.x * blockDim.x + threadIdx.x;
    if (e < E) {
        int r = row[e], c = col[e];
        int p = atomicAdd(&fill[c], 1);
        srcv[p] = r;
        wcsc[p] = dinv[r] * w[e] * dinv[c];
    }
}

__global__ void fill_self_kernel(const float* __restrict__ dinv, int* fill,
                                 int* srcv, float* wcsc, int n) {
    int i = blockIdx.x * blockDim.x + threadIdx.x;
    if (i < n) {
        int p = atomicAdd(&fill[i], 1);
        srcv[p] = i;
        wcsc[p] = dinv[i] * dinv[i];
    }
}

// zero padding rows [N, MAXN) of h, h0, ag so guard-free GEMMs read zeros
__global__ void pad_kernel(float* h, float* h0, float* ag, int startElem, int totalElem) {
    int i = blockIdx.x * blockDim.x + threadIdx.x + startElem;
    if (i < totalElem) { h[i] = 0.0f; h0[i] = 0.0f; ag[i] = 0.0f; }
}

// ---------------- fp32 SGEMM tiles (input / output linears) ----------------
#define BM 128
#define BN 128
#define BK 8
#define TM 8
#define TN 8

// ---- input linear: h = h0 = relu(x @ w_in + b), guarded (x has exactly M rows) ----
__global__ void __launch_bounds__(256, 2)
gemm_in(const float* __restrict__ A, const float* __restrict__ W,
        const float* __restrict__ bias, float* __restrict__ out,
        float* __restrict__ out2, int M) {
    __shared__ float As[BK][BM];
    __shared__ float Bs[BK][BN];
    const int tid = threadIdx.x;
    const int tx = tid & 15, ty = tid >> 4;
    const int m0 = blockIdx.x * BM;
    const int arow = tid >> 1, acol4 = (tid & 1) * 4;
    const int brow = tid >> 5, bcol4 = (tid & 31) * 4;

    float acc[TM][TN];
#pragma unroll
    for (int i = 0; i < TM; i++)
#pragma unroll
        for (int j = 0; j < TN; j++) acc[i][j] = 0.0f;

    for (int k0 = 0; k0 < HDIM; k0 += BK) {
        float4 av = make_float4(0.f, 0.f, 0.f, 0.f);
        int am = m0 + arow;
        if (am < M) av = *reinterpret_cast<const float4*>(A + (size_t)am * HDIM + k0 + acol4);
        As[acol4 + 0][arow] = av.x; As[acol4 + 1][arow] = av.y;
        As[acol4 + 2][arow] = av.z; As[acol4 + 3][arow] = av.w;

        float4 bv = *reinterpret_cast<const float4*>(W + (size_t)(k0 + brow) * HDIM + bcol4);
        Bs[brow][bcol4 + 0] = bv.x; Bs[brow][bcol4 + 1] = bv.y;
        Bs[brow][bcol4 + 2] = bv.z; Bs[brow][bcol4 + 3] = bv.w;
        __syncthreads();

#pragma unroll
        for (int kk = 0; kk < BK; kk++) {
            float ra[TM], rb[TN];
#pragma unroll
            for (int i = 0; i < TM; i++) ra[i] = As[kk][ty * TM + i];
#pragma unroll
            for (int j = 0; j < TN; j++) rb[j] = Bs[kk][tx * TN + j];
#pragma unroll
            for (int i = 0; i < TM; i++)
#pragma unroll
                for (int j = 0; j < TN; j++) acc[i][j] += ra[i] * rb[j];
        }
        __syncthreads();
    }

    float b0[TN];
#pragma unroll
    for (int j = 0; j < TN; j++) b0[j] = bias[tx * TN + j];

#pragma unroll
    for (int i = 0; i < TM; i++) {
        int m = m0 + ty * TM + i;
        if (m >= M) continue;
        float4 o0, o1;
        o0.x = fmaxf(acc[i][0] + b0[0], 0.f); o0.y = fmaxf(acc[i][1] + b0[1], 0.f);
        o0.z = fmaxf(acc[i][2] + b0[2], 0.f); o0.w = fmaxf(acc[i][3] + b0[3], 0.f);
        o1.x = fmaxf(acc[i][4] + b0[4], 0.f); o1.y = fmaxf(acc[i][5] + b0[5], 0.f);
        o1.z = fmaxf(acc[i][6] + b0[6], 0.f); o1.w = fmaxf(acc[i][7] + b0[7], 0.f);
        float4* p  = reinterpret_cast<float4*>(out  + (size_t)m * HDIM + tx * TN);
        float4* p2 = reinterpret_cast<float4*>(out2 + (size_t)m * HDIM + tx * TN);
        p[0] = o0; p[1] = o1; p2[0] = o0; p2[1] = o1;
    }
}

// ---- output linear: out[M,64] = h @ w_out + b_out ----
__global__ void __launch_bounds__(256, 2)
gemm_out(const float* __restrict__ A, const float* __restrict__ W,
         const float* __restrict__ bias, float* __restrict__ out, int M) {
    __shared__ float As[BK][BM];
    __shared__ float Bs[BK][BN];
    const int tid = threadIdx.x;
    const int tx = tid & 15, ty = tid >> 4;
    const int m0 = blockIdx.x * BM;
    const int arow = tid >> 1, acol4 = (tid & 1) * 4;
    const int brow = tid >> 5, bcol4 = (tid & 31) * 4;
    const int Nn = 64;

    float acc[TM][TN];
#pragma unroll
    for (int i = 0; i < TM; i++)
#pragma unroll
        for (int j = 0; j < TN; j++) acc[i][j] = 0.0f;

    for (int k0 = 0; k0 < HDIM; k0 += BK) {
        float4 av = *reinterpret_cast<const float4*>(A + (size_t)(m0 + arow) * HDIM + k0 + acol4);
        As[acol4 + 0][arow] = av.x; As[acol4 + 1][arow] = av.y;
        As[acol4 + 2][arow] = av.z; As[acol4 + 3][arow] = av.w;

        float4 bv = make_float4(0.f, 0.f, 0.f, 0.f);
        if (bcol4 < Nn) bv = *reinterpret_cast<const float4*>(W + (size_t)(k0 + brow) * Nn + bcol4);
        Bs[brow][bcol4 + 0] = bv.x; Bs[brow][bcol4 + 1] = bv.y;
        Bs[brow][bcol4 + 2] = bv.z; Bs[brow][bcol4 + 3] = bv.w;
        __syncthreads();

#pragma unroll
        for (int kk = 0; kk < BK; kk++) {
            float ra[TM], rb[TN];
#pragma unroll
            for (int i = 0; i < TM; i++) ra[i] = As[kk][ty * TM + i];
#pragma unroll
            for (int j = 0; j < TN; j++) rb[j] = Bs[kk][tx * TN + j];
#pragma unroll
            for (int i = 0; i < TM; i++)
#pragma unroll
                for (int j = 0; j < TN; j++) acc[i][j] += ra[i] * rb[j];
        }
        __syncthreads();
    }

    if (tx < 8) {   // only columns < 64
        float b0[TN];
#pragma unroll
        for (int j = 0; j < TN; j++) b0[j] = bias[tx * TN + j];
#pragma unroll
        for (int i = 0; i < TM; i++) {
            int m = m0 + ty * TM + i;
            if (m >= M) continue;
            float4 o0, o1;
            o0.x = acc[i][0] + b0[0]; o0.y = acc[i][1] + b0[1];
            o0.z = acc[i][2] + b0[2]; o0.w = acc[i][3] + b0[3];
            o1.x = acc[i][4] + b0[4]; o1.y = acc[i][5] + b0[5];
            o1.z = acc[i][6] + b0[6]; o1.w = acc[i][7] + b0[7];
            float4* p = reinterpret_cast<float4*>(out + (size_t)m * Nn + tx * TN);
            p[0] = o0; p[1] = o1;
        }
    }
}

// ---------------- tf32 tensor-core fused layer GEMM ----------------
// h_out = relu( cs*ag + ci*h0 + beta*( ag@W1 + h0@W2 ) )   (guard-free padded M)
// CTA: 128x128 tile, 8 warps in 4x2 grid; warp tile 32x64 = 2x4 wmma 16x16 frags.
// Accumulators initialized from global residual (cs*ag + ci*h0); beta folded into
// the B tile at smem load; relu elementwise on the accumulator; store direct to
// global. Static smem: 128*24 + 16*136 = 5248 floats = 21 KB.
#define SA_LD 24     // A tile leading dim (16 k + 8 pad), 96 B = mult of 16 B
#define SB_LD 136    // B tile leading dim (128 n + 8 pad), 544 B = mult of 16 B

__global__ void __launch_bounds__(256)
gemm_layer_tc(const float* __restrict__ ag, const float* __restrict__ h0,
              const float* __restrict__ W1, const float* __restrict__ W2,
              float* __restrict__ hout, float cs, float ci, float beta) {
    __shared__ float sA[128 * SA_LD];
    __shared__ float sB[16 * SB_LD];

    const int tid = threadIdx.x;
    const int wid = tid >> 5;
    const int warp_m = wid >> 1;          // 0..3
    const int warp_n = wid & 1;           // 0..1
    const int m0 = blockIdx.x * 128;

    // ---- init accumulators with the exact-fp32 residual: cs*ag + ci*h0 ----
    wmma::fragment<wmma::accumulator, 16, 16, 8, float> C[2][4];
#pragma unroll
    for (int mi = 0; mi < 2; mi++) {
        const size_t rbase = (size_t)(m0 + warp_m * 32 + mi * 16) * HDIM;
#pragma unroll
        for (int ni = 0; ni < 4; ni++) {
            const int coff = warp_n * 64 + ni * 16;
            wmma::fragment<wmma::accumulator, 16, 16, 8, float> Ra, Rb;
            wmma::load_matrix_sync(Ra, ag + rbase + coff, HDIM, wmma::mem_row_major);
            wmma::load_matrix_sync(Rb, h0 + rbase + coff, HDIM, wmma::mem_row_major);
#pragma unroll
            for (int t = 0; t < Ra.num_elements; t++)
                C[mi][ni].x[t] = cs * Ra.x[t] + ci * Rb.x[t];
        }
    }

    // tile-load thread mapping
    const int a_row = tid >> 1, a_seg = (tid & 1) * 8;        // A: 2 thr/row, 8 floats each
    const int b_row = tid >> 4, b_col = (tid & 15) * 8;       // B: 16 thr/row, 8 floats each

#pragma unroll 1
    for (int half = 0; half < 2; half++) {
        const float* Abase = (half ? h0 : ag) + (size_t)m0 * HDIM;
        const float* Wbase = half ? W2 : W1;
#pragma unroll 1
        for (int k0 = 0; k0 < HDIM; k0 += 16) {
            __syncthreads();
            // load A tile: rows 0..127, k columns k0..k0+15
            {
                const float4* p = reinterpret_cast<const float4*>(Abase + (size_t)a_row * HDIM + k0 + a_seg);
                float4 v0 = p[0], v1 = p[1];
                float* d = sA + a_row * SA_LD + a_seg;
                d[0] = v0.x; d[1] = v0.y; d[2] = v0.z; d[3] = v0.w;
                d[4] = v1.x; d[5] = v1.y; d[6] = v1.z; d[7] = v1.w;
            }
            // load B tile scaled by beta: W rows k0..k0+15, all 128 columns
            {
                const float4* p = reinterpret_cast<const float4*>(Wbase + (size_t)(k0 + b_row) * HDIM + b_col);
                float4 v0 = p[0], v1 = p[1];
                float* d = sB + b_row * SB_LD + b_col;
                d[0] = beta * v0.x; d[1] = beta * v0.y; d[2] = beta * v0.z; d[3] = beta * v0.w;
                d[4] = beta * v1.x; d[5] = beta * v1.y; d[6] = beta * v1.z; d[7] = beta * v1.w;
            }
            __syncthreads();

#pragma unroll
            for (int kk = 0; kk < 16; kk += 8) {
                wmma::fragment<wmma::matrix_a, 16, 16, 8, wmma::precision::tf32, wmma::row_major> a[2];
#pragma unroll
                for (int mi = 0; mi < 2; mi++) {
                    wmma::load_matrix_sync(a[mi], sA + (warp_m * 32 + mi * 16) * SA_LD + kk, SA_LD);
#pragma unroll
                    for (int t = 0; t < a[mi].num_elements; t++)
                        a[mi].x[t] = wmma::__float_to_tf32(a[mi].x[t]);
                }
#pragma unroll
                for (int ni = 0; ni < 4; ni++) {
                    wmma::fragment<wmma::matrix_b, 16, 16, 8, wmma::precision::tf32, wmma::row_major> b;
                    wmma::load_matrix_sync(b, sB + kk * SB_LD + warp_n * 64 + ni * 16, SB_LD);
#pragma unroll
                    for (int t = 0; t < b.num_elements; t++)
                        b.x[t] = wmma::__float_to_tf32(b.x[t]);
#pragma unroll
                    for (int mi = 0; mi < 2; mi++)
                        wmma::mma_sync(C[mi][ni], a[mi], b, C[mi][ni]);
                }
            }
        }
    }

    // ---- relu elementwise on accumulators, store straight to global ----
#pragma unroll
    for (int mi = 0; mi < 2; mi++) {
        const size_t rbase = (size_t)(m0 + warp_m * 32 + mi * 16) * HDIM;
#pragma unroll
        for (int ni = 0; ni < 4; ni++) {
#pragma unroll
            for (int t = 0; t < C[mi][ni].num_elements; t++)
                C[mi][ni].x[t] = fmaxf(C[mi][ni].x[t], 0.0f);
            wmma::store_matrix_sync(hout + rbase + warp_n * 64 + ni * 16,
                                    C[mi][ni], HDIM, wmma::mem_row_major);
        }
    }
}

// ---------------- atomic-free CSC aggregation: ag[c,:] = sum_j wc[j]*h[src[j],:] ----
__global__ void agg_kernel(const float* __restrict__ h,
                           const int* __restrict__ off, const int* __restrict__ src,
                           const float* __restrict__ wc, float* __restrict__ ag, int n) {
    int node = (blockIdx.x * blockDim.x + threadIdx.x) >> 5;
    int lane = threadIdx.x & 31;
    if (node >= n) return;
    int s = off[node], e = off[node + 1];
    const float4* H4 = reinterpret_cast<const float4*>(h);
    float4 acc = make_float4(0.f, 0.f, 0.f, 0.f);
    int j = s;
    for (; j + 1 < e; j += 2) {
        int s0 = src[j], s1 = src[j + 1];
        float w0 = wc[j], w1 = wc[j + 1];
        float4 v0 = H4[(size_t)s0 * 32 + lane];
        float4 v1 = H4[(size_t)s1 * 32 + lane];
        acc.x += w0 * v0.x; acc.y += w0 * v0.y; acc.z += w0 * v0.z; acc.w += w0 * v0.w;
        acc.x += w1 * v1.x; acc.y += w1 * v1.y; acc.z += w1 * v1.z; acc.w += w1 * v1.w;
    }
    if (j < e) {
        float w0 = wc[j];
        float4 v0 = H4[(size_t)src[j] * 32 + lane];
        acc.x += w0 * v0.x; acc.y += w0 * v0.y; acc.z += w0 * v0.z; acc.w += w0 * v0.w;
    }
    reinterpret_cast<float4*>(ag)[(size_t)node * 32 + lane] = acc;
}

// ---------------- log_softmax over 64 classes, in place ----------------
__global__ void logsoftmax64_kernel(float* __restrict__ out, int n) {
    int row = blockIdx.x * 8 + (threadIdx.x >> 5);
    int lane = threadIdx.x & 31;
    if (row >= n) return;
    float* p = out + (size_t)row * 64;
    float a = p[lane], b = p[lane + 32];
    float mx = fmaxf(a, b);
#pragma unroll
    for (int d = 16; d; d >>= 1) mx = fmaxf(mx, __shfl_xor_sync(0xFFFFFFFFu, mx, d));
    float s = __expf(a - mx) + __expf(b - mx);
#pragma unroll
    for (int d = 16; d; d >>= 1) s += __shfl_xor_sync(0xFFFFFFFFu, s, d);
    float lse = mx + __logf(s);
    p[lane] = a - lse;
    p[lane + 32] = b - lse;
}

// ---------------- launch ----------------
extern "C" void kernel_launch(void* const* d_in, const int* in_sizes, int n_in,
                              void* d_out, int out_size) {
    const float* x     = (const float*)d_in[0];
    const int*   ei    = (const int*)  d_in[1];
    const float* ew    = (const float*)d_in[2];
    const float* w_in  = (const float*)d_in[3];
    const float* b_in  = (const float*)d_in[4];
    const float* ws1   = (const float*)d_in[5];
    const float* ws2   = (const float*)d_in[6];
    const float* w_out = (const float*)d_in[7];
    const float* b_out = (const float*)d_in[8];

    const int N = in_sizes[0] / HDIM;            // 50000
    const int E = in_sizes[2];                   // 640000
    const int L = in_sizes[5] / (HDIM * HDIM);   // 16
    const float ALPHA = 0.1f;
    const double LAMDA = 0.5;

    const int* erow = ei;
    const int* ecol = ei + E;

    float *deg, *dinv, *wc, *h, *h0, *ag;
    int *cnt, *off, *fill, *src;
    cudaGetSymbolAddress((void**)&deg,  g_deg);
    cudaGetSymbolAddress((void**)&dinv, g_dinv);
    cudaGetSymbolAddress((void**)&cnt,  g_cnt);
    cudaGetSymbolAddress((void**)&off,  g_off);
    cudaGetSymbolAddress((void**)&fill, g_fill);
    cudaGetSymbolAddress((void**)&src,  g_src);
    cudaGetSymbolAddress((void**)&wc,   g_wc);
    cudaGetSymbolAddress((void**)&h,    g_h);
    cudaGetSymbolAddress((void**)&h0,   g_h0);
    cudaGetSymbolAddress((void**)&ag,   g_ag);

    const int TB = 256;
    const int gN = (N + TB - 1) / TB;
    const int gE = (E + TB - 1) / TB;
    const int nb = (N + 1023) / 1024;            // 49 scan blocks

    // ---- graph normalization + CSC build ----
    init_kernel<<<gN, TB>>>(deg, cnt, N);
    edge_count_kernel<<<gE, TB>>>(erow, ecol, ew, deg, cnt, E);
    dinv_kernel<<<gN, TB>>>(deg, dinv, N);
    scan_block_kernel<<<nb, 1024>>>(cnt, off, N);
    scan_bsums_kernel<<<1, 32>>>(nb);
    scan_fixup_kernel<<<nb, 1024>>>(off, fill, N, nb);
    fill_edges_kernel<<<gE, TB>>>(erow, ecol, ew, dinv, fill, src, wc, E);
    fill_self_kernel<<<gN, TB>>>(dinv, fill, src, wc, N);

    // zero padding rows of h/h0/ag
    {
        int startElem = N * HDIM;
        int padElems = NFEAT_PAD - startElem;
        pad_kernel<<<(padElems + TB - 1) / TB, TB>>>(h, h0, ag, startElem, NFEAT_PAD);
    }

    const int gGemm = MAXN / BM;   // 391, covers padded rows

    // ---- input linear + relu; h and h0 (guarded on M=N) ----
    gemm_in<<<gGemm, 256>>>(x, w_in, b_in, h, h0, N);

    // ---- GCNII layers: ag = A_hat@h, then fused tf32 K=256 GEMM ----
    for (int i = 0; i < L; i++) {
        float beta = (float)log(LAMDA / (double)(i + 1) + 1.0);
        float cs = (1.0f - beta) * (1.0f - ALPHA);
        float ci = (1.0f - beta) * ALPHA;
        agg_kernel<<<(N * 32 + 255) / 256, 256>>>(h, off, src, wc, ag, N);
        gemm_layer_tc<<<gGemm, 256>>>(ag, h0,
                                      ws1 + (size_t)i * HDIM * HDIM,
                                      ws2 + (size_t)i * HDIM * HDIM,
                                      h, cs, ci, beta);
    }

    // ---- output linear + log_softmax ----
    float* outp = (float*)d_out;
    gemm_out<<<gGemm, 256>>>(h, w_out, b_out, outp, N);
    logsoftmax64_kernel<<<(N + 7) / 8, 256>>>(outp, N);
}